// round 1
// baseline (speedup 1.0000x reference)
#include <cuda_runtime.h>

#define TPB 256
#define NEG_SLOPE 0.01f

// ---- shared-memory layout (float offsets) ----
#define OFF_W0   0        // 60*32 = 1920
#define OFF_B0   1920     // 32
#define OFF_W1   1952     // 4 hidden layers: (1024 w + 32 b) each
#define HID_STRIDE 1056
#define OFF_W5   6176     // 32*8 = 256
#define OFF_B5   6432     // 8
#define OFF_BANK 6440     // 8*1024 = 8192
#define PARAM_FLOATS 14632
#define ACT_STRIDE 33     // 32 + 1 pad -> conflict-free per-thread rows
#define OFF_ACT  PARAM_FLOATS
#define SMEM_FLOATS (PARAM_FLOATS + TPB * ACT_STRIDE)

__device__ __forceinline__ float lrelu(float v) {
    // v>=0: max(v, .01v)=v ; v<0: max(v,.01v)=.01v
    return fmaxf(v, NEG_SLOPE * v);
}

// acc[32] += xk * wrow[0..31]   (wrow 16B-aligned in smem)
__device__ __forceinline__ void fma_row32(float acc[32], float xk, const float* wrow) {
    const float4* wr = reinterpret_cast<const float4*>(wrow);
#pragma unroll
    for (int j = 0; j < 8; j++) {
        float4 w = wr[j];
        acc[4 * j + 0] += xk * w.x;
        acc[4 * j + 1] += xk * w.y;
        acc[4 * j + 2] += xk * w.z;
        acc[4 * j + 3] += xk * w.w;
    }
}

__global__ __launch_bounds__(TPB, 2)
void pointconv_fused_kernel(
    const float* __restrict__ rel,   // [n,60]
    const float* __restrict__ feat,  // [n,32]
    const float* __restrict__ w0, const float* __restrict__ b0,
    const float* __restrict__ w1, const float* __restrict__ b1,
    const float* __restrict__ w2, const float* __restrict__ b2,
    const float* __restrict__ w3, const float* __restrict__ b3,
    const float* __restrict__ w4, const float* __restrict__ b4,
    const float* __restrict__ w5, const float* __restrict__ b5,
    const float* __restrict__ bank,  // [8,1024]
    float* __restrict__ out,         // [n,32]
    int n)
{
    extern __shared__ float sm[];
    const int tid = threadIdx.x;

    // ---- cooperative param staging ----
#define CP(off, src, cnt) for (int t = tid; t < (cnt); t += TPB) sm[(off) + t] = (src)[t];
    CP(OFF_W0, w0, 1920)
    CP(OFF_B0, b0, 32)
    CP(OFF_W1 + 0 * HID_STRIDE, w1, 1024) CP(OFF_W1 + 0 * HID_STRIDE + 1024, b1, 32)
    CP(OFF_W1 + 1 * HID_STRIDE, w2, 1024) CP(OFF_W1 + 1 * HID_STRIDE + 1024, b2, 32)
    CP(OFF_W1 + 2 * HID_STRIDE, w3, 1024) CP(OFF_W1 + 2 * HID_STRIDE + 1024, b3, 32)
    CP(OFF_W1 + 3 * HID_STRIDE, w4, 1024) CP(OFF_W1 + 3 * HID_STRIDE + 1024, b4, 32)
    CP(OFF_W5, w5, 256)
    CP(OFF_B5, b5, 8)
    CP(OFF_BANK, bank, 8192)
#undef CP
    __syncthreads();

    const int i = blockIdx.x * TPB + tid;
    if (i >= n) return;

    float* act = &sm[OFF_ACT + tid * ACT_STRIDE];
    float acc[32];

    // ---- layer 0: 60 -> 32, streamed from global (no x[] register array) ----
    {
        const float4* rp = reinterpret_cast<const float4*>(rel + (size_t)i * 60);
#pragma unroll
        for (int j = 0; j < 32; j++) acc[j] = sm[OFF_B0 + j];
        for (int k4 = 0; k4 < 15; k4++) {
            float4 xv = rp[k4];
            const float* wrow = &sm[OFF_W0 + (k4 * 4) * 32];
            fma_row32(acc, xv.x, wrow + 0 * 32);
            fma_row32(acc, xv.y, wrow + 1 * 32);
            fma_row32(acc, xv.z, wrow + 2 * 32);
            fma_row32(acc, xv.w, wrow + 3 * 32);
        }
#pragma unroll
        for (int j = 0; j < 32; j++) act[j] = lrelu(acc[j]);
    }

    // ---- hidden layers 1..4: 32 -> 32 ----
    for (int L = 0; L < 4; L++) {
        const float* wb = &sm[OFF_W1 + L * HID_STRIDE];
#pragma unroll
        for (int j = 0; j < 32; j++) acc[j] = wb[1024 + j];
#pragma unroll 4
        for (int k = 0; k < 32; k++) {
            fma_row32(acc, act[k], &wb[k * 32]);
        }
#pragma unroll
        for (int j = 0; j < 32; j++) act[j] = lrelu(acc[j]);
    }

    // ---- layer 5: 32 -> 8 logits ----
    float lg[8];
#pragma unroll
    for (int w = 0; w < 8; w++) lg[w] = sm[OFF_B5 + w];
#pragma unroll 4
    for (int k = 0; k < 32; k++) {
        float xk = act[k];
        const float4* wr = reinterpret_cast<const float4*>(&sm[OFF_W5 + k * 8]);
        float4 a = wr[0], b = wr[1];
        lg[0] += xk * a.x; lg[1] += xk * a.y; lg[2] += xk * a.z; lg[3] += xk * a.w;
        lg[4] += xk * b.x; lg[5] += xk * b.y; lg[6] += xk * b.z; lg[7] += xk * b.w;
    }

    // ---- softmax over 8 (fp32) ----
    float m = lg[0];
#pragma unroll
    for (int w = 1; w < 8; w++) m = fmaxf(m, lg[w]);
    float cf[8], s = 0.0f;
#pragma unroll
    for (int w = 0; w < 8; w++) { cf[w] = __expf(lg[w] - m); s += cf[w]; }
    float inv = 1.0f / s;
#pragma unroll
    for (int w = 0; w < 8; w++) act[w] = cf[w] * inv;  // park coeff in smem row

    // ---- bank apply: out[o] = sum_w cf[w] * sum_k feat[k]*bank[w, k*32+o] ----
    float o_[32];
#pragma unroll
    for (int j = 0; j < 32; j++) o_[j] = 0.0f;

    const float4* fp = reinterpret_cast<const float4*>(feat + (size_t)i * 32);
    for (int w = 0; w < 8; w++) {
        float cw = act[w];
        const float* bw = &sm[OFF_BANK + w * 1024];
        for (int k4 = 0; k4 < 8; k4++) {
            float4 fv = fp[k4];                 // L1 hit after first pass
            const float* br = &bw[(k4 * 4) * 32];
            fma_row32(o_, cw * fv.x, br + 0 * 32);
            fma_row32(o_, cw * fv.y, br + 1 * 32);
            fma_row32(o_, cw * fv.z, br + 2 * 32);
            fma_row32(o_, cw * fv.w, br + 3 * 32);
        }
    }

    // ---- store [32] fp32 ----
    float4* op = reinterpret_cast<float4*>(out + (size_t)i * 32);
#pragma unroll
    for (int j4 = 0; j4 < 8; j4++) {
        op[j4] = make_float4(o_[4 * j4 + 0], o_[4 * j4 + 1], o_[4 * j4 + 2], o_[4 * j4 + 3]);
    }
}

extern "C" void kernel_launch(void* const* d_in, const int* in_sizes, int n_in,
                              void* d_out, int out_size) {
    const float* rel  = (const float*)d_in[0];
    const float* feat = (const float*)d_in[1];
    const float* w0 = (const float*)d_in[2];  const float* b0 = (const float*)d_in[3];
    const float* w1 = (const float*)d_in[4];  const float* b1 = (const float*)d_in[5];
    const float* w2 = (const float*)d_in[6];  const float* b2 = (const float*)d_in[7];
    const float* w3 = (const float*)d_in[8];  const float* b3 = (const float*)d_in[9];
    const float* w4 = (const float*)d_in[10]; const float* b4 = (const float*)d_in[11];
    const float* w5 = (const float*)d_in[12]; const float* b5 = (const float*)d_in[13];
    const float* bank = (const float*)d_in[14];

    int n = in_sizes[0] / 60;
    size_t smem = (size_t)SMEM_FLOATS * sizeof(float);  // 92,320 B

    cudaFuncSetAttribute(pointconv_fused_kernel,
                         cudaFuncAttributeMaxDynamicSharedMemorySize, (int)smem);

    dim3 grid((n + TPB - 1) / TPB);
    pointconv_fused_kernel<<<grid, TPB, smem>>>(
        rel, feat, w0, b0, w1, b1, w2, b2, w3, b3, w4, b4, w5, b5, bank,
        (float*)d_out, n);
}

// round 2
// speedup vs baseline: 1.4223x; 1.4223x over previous
#include <cuda_runtime.h>

#define TPB 128
#define PPT 2            // points per thread
#define NEG_SLOPE 0.01f

// ---- shared-memory layout (float offsets) ----
#define OFF_W0   0        // 60*32 = 1920
#define OFF_B0   1920     // 32
#define OFF_W1   1952     // 4 hidden layers: (1024 w + 32 b) each
#define HID_STRIDE 1056
#define OFF_W5   6176     // 32*8 = 256
#define OFF_B5   6432     // 8
#define OFF_BANK 6440     // 8*1024 = 8192
#define PARAM_FLOATS 14632
#define OFF_ACT  PARAM_FLOATS
#define ACT_STRIDE 41     // 32 acts/feat + 8 coeffs + 1 pad; gcd(41,32)=1 -> conflict-free
#define SMEM_FLOATS (PARAM_FLOATS + TPB * PPT * ACT_STRIDE)

typedef unsigned long long u64;

__device__ __forceinline__ u64 ffma2(u64 a, u64 b, u64 c) {
    u64 d;
    asm("fma.rn.f32x2 %0, %1, %2, %3;" : "=l"(d) : "l"(a), "l"(b), "l"(c));
    return d;
}
__device__ __forceinline__ u64 dup2(float x) {
    u64 d;
    asm("mov.b64 %0, {%1, %2};" : "=l"(d) : "f"(x), "f"(x));
    return d;
}
__device__ __forceinline__ float2 unpk(u64 d) {
    float2 r;
    asm("mov.b64 {%0, %1}, %2;" : "=f"(r.x), "=f"(r.y) : "l"(d));
    return r;
}
__device__ __forceinline__ float lrelu(float v) { return fmaxf(v, NEG_SLOPE * v); }

// acc{0,1}[16 pairs] += dup(x{0,1}) * wrow[32 floats]; weight pairs come free from LDS.128
__device__ __forceinline__ void fma_row(u64 acc0[16], u64 acc1[16],
                                        u64 x0, u64 x1, const float* wrow) {
    const ulonglong2* wr = reinterpret_cast<const ulonglong2*>(wrow);
#pragma unroll
    for (int j = 0; j < 8; j++) {
        ulonglong2 w = wr[j];
        acc0[2 * j]     = ffma2(x0, w.x, acc0[2 * j]);
        acc0[2 * j + 1] = ffma2(x0, w.y, acc0[2 * j + 1]);
        acc1[2 * j]     = ffma2(x1, w.x, acc1[2 * j]);
        acc1[2 * j + 1] = ffma2(x1, w.y, acc1[2 * j + 1]);
    }
}

__global__ __launch_bounds__(TPB, 2)
void pointconv_fused_kernel(
    const float* __restrict__ rel,   // [n,60]
    const float* __restrict__ feat,  // [n,32]
    const float* __restrict__ w0, const float* __restrict__ b0,
    const float* __restrict__ w1, const float* __restrict__ b1,
    const float* __restrict__ w2, const float* __restrict__ b2,
    const float* __restrict__ w3, const float* __restrict__ b3,
    const float* __restrict__ w4, const float* __restrict__ b4,
    const float* __restrict__ w5, const float* __restrict__ b5,
    const float* __restrict__ bank,  // [8,1024]
    float* __restrict__ out,         // [n,32]
    int n)
{
    extern __shared__ float sm[];
    const int tid = threadIdx.x;

    // ---- cooperative param staging ----
#define CP(off, src, cnt) for (int t = tid; t < (cnt); t += TPB) sm[(off) + t] = (src)[t];
    CP(OFF_W0, w0, 1920)
    CP(OFF_B0, b0, 32)
    CP(OFF_W1 + 0 * HID_STRIDE, w1, 1024) CP(OFF_W1 + 0 * HID_STRIDE + 1024, b1, 32)
    CP(OFF_W1 + 1 * HID_STRIDE, w2, 1024) CP(OFF_W1 + 1 * HID_STRIDE + 1024, b2, 32)
    CP(OFF_W1 + 2 * HID_STRIDE, w3, 1024) CP(OFF_W1 + 2 * HID_STRIDE + 1024, b3, 32)
    CP(OFF_W1 + 3 * HID_STRIDE, w4, 1024) CP(OFF_W1 + 3 * HID_STRIDE + 1024, b4, 32)
    CP(OFF_W5, w5, 256)
    CP(OFF_B5, b5, 8)
    CP(OFF_BANK, bank, 8192)
#undef CP
    __syncthreads();

    const int i0 = blockIdx.x * (TPB * PPT) + tid;   // first point
    const int i1 = i0 + TPB;                          // second point (coalesced)
    if (i1 >= n && i0 >= n) return;

    float* act0 = &sm[OFF_ACT + (0 * TPB + tid) * ACT_STRIDE];
    float* act1 = &sm[OFF_ACT + (1 * TPB + tid) * ACT_STRIDE];

    u64 acc0[16], acc1[16];

    // ---- layer 0: 60 -> 32 ----
    {
        const float4* rp0 = reinterpret_cast<const float4*>(rel + (size_t)i0 * 60);
        const float4* rp1 = reinterpret_cast<const float4*>(rel + (size_t)i1 * 60);
        const ulonglong2* bp = reinterpret_cast<const ulonglong2*>(&sm[OFF_B0]);
#pragma unroll
        for (int j = 0; j < 8; j++) {
            ulonglong2 b = bp[j];
            acc0[2 * j] = b.x; acc0[2 * j + 1] = b.y;
            acc1[2 * j] = b.x; acc1[2 * j + 1] = b.y;
        }
        for (int k4 = 0; k4 < 15; k4++) {
            float4 a0 = rp0[k4];
            float4 a1 = rp1[k4];
            const float* wrow = &sm[OFF_W0 + (k4 * 4) * 32];
            fma_row(acc0, acc1, dup2(a0.x), dup2(a1.x), wrow + 0 * 32);
            fma_row(acc0, acc1, dup2(a0.y), dup2(a1.y), wrow + 1 * 32);
            fma_row(acc0, acc1, dup2(a0.z), dup2(a1.z), wrow + 2 * 32);
            fma_row(acc0, acc1, dup2(a0.w), dup2(a1.w), wrow + 3 * 32);
        }
#pragma unroll
        for (int j = 0; j < 16; j++) {
            float2 v0 = unpk(acc0[j]), v1 = unpk(acc1[j]);
            act0[2 * j] = lrelu(v0.x); act0[2 * j + 1] = lrelu(v0.y);
            act1[2 * j] = lrelu(v1.x); act1[2 * j + 1] = lrelu(v1.y);
        }
    }

    // ---- hidden layers 1..4: 32 -> 32 ----
    for (int L = 0; L < 4; L++) {
        const float* wb = &sm[OFF_W1 + L * HID_STRIDE];
        const ulonglong2* bp = reinterpret_cast<const ulonglong2*>(&wb[1024]);
#pragma unroll
        for (int j = 0; j < 8; j++) {
            ulonglong2 b = bp[j];
            acc0[2 * j] = b.x; acc0[2 * j + 1] = b.y;
            acc1[2 * j] = b.x; acc1[2 * j + 1] = b.y;
        }
#pragma unroll 4
        for (int k = 0; k < 32; k++) {
            fma_row(acc0, acc1, dup2(act0[k]), dup2(act1[k]), &wb[k * 32]);
        }
#pragma unroll
        for (int j = 0; j < 16; j++) {
            float2 v0 = unpk(acc0[j]), v1 = unpk(acc1[j]);
            act0[2 * j] = lrelu(v0.x); act0[2 * j + 1] = lrelu(v0.y);
            act1[2 * j] = lrelu(v1.x); act1[2 * j + 1] = lrelu(v1.y);
        }
    }

    // ---- layer 5: 32 -> 8 logits (pairs over the 8 outputs) ----
    u64 lg0[4], lg1[4];
    {
        const ulonglong2* bp = reinterpret_cast<const ulonglong2*>(&sm[OFF_B5]);
        ulonglong2 b0p = bp[0], b1p = bp[1];
        lg0[0] = b0p.x; lg0[1] = b0p.y; lg0[2] = b1p.x; lg0[3] = b1p.y;
        lg1[0] = b0p.x; lg1[1] = b0p.y; lg1[2] = b1p.x; lg1[3] = b1p.y;
#pragma unroll 4
        for (int k = 0; k < 32; k++) {
            u64 x0 = dup2(act0[k]), x1 = dup2(act1[k]);
            const ulonglong2* wr = reinterpret_cast<const ulonglong2*>(&sm[OFF_W5 + k * 8]);
            ulonglong2 wa = wr[0], wb2 = wr[1];
            lg0[0] = ffma2(x0, wa.x, lg0[0]); lg0[1] = ffma2(x0, wa.y, lg0[1]);
            lg0[2] = ffma2(x0, wb2.x, lg0[2]); lg0[3] = ffma2(x0, wb2.y, lg0[3]);
            lg1[0] = ffma2(x1, wa.x, lg1[0]); lg1[1] = ffma2(x1, wa.y, lg1[1]);
            lg1[2] = ffma2(x1, wb2.x, lg1[2]); lg1[3] = ffma2(x1, wb2.y, lg1[3]);
        }
    }

    // ---- softmax over 8 (scalar fp32); coeffs parked at act[32..39] ----
    {
        float l0[8], l1[8];
#pragma unroll
        for (int j = 0; j < 4; j++) {
            float2 v0 = unpk(lg0[j]), v1 = unpk(lg1[j]);
            l0[2 * j] = v0.x; l0[2 * j + 1] = v0.y;
            l1[2 * j] = v1.x; l1[2 * j + 1] = v1.y;
        }
        float m0 = l0[0], m1 = l1[0];
#pragma unroll
        for (int w = 1; w < 8; w++) { m0 = fmaxf(m0, l0[w]); m1 = fmaxf(m1, l1[w]); }
        float s0 = 0.f, s1 = 0.f;
#pragma unroll
        for (int w = 0; w < 8; w++) {
            l0[w] = __expf(l0[w] - m0); s0 += l0[w];
            l1[w] = __expf(l1[w] - m1); s1 += l1[w];
        }
        float r0 = 1.0f / s0, r1 = 1.0f / s1;
#pragma unroll
        for (int w = 0; w < 8; w++) { act0[32 + w] = l0[w] * r0; act1[32 + w] = l1[w] * r1; }
    }

    // ---- copy feat into act[0..31] (acts dead now) ----
    {
        const float4* fp0 = reinterpret_cast<const float4*>(feat + (size_t)i0 * 32);
        const float4* fp1 = reinterpret_cast<const float4*>(feat + (size_t)i1 * 32);
#pragma unroll
        for (int q = 0; q < 8; q++) {
            float4 f0 = fp0[q], f1 = fp1[q];
            act0[4 * q + 0] = f0.x; act0[4 * q + 1] = f0.y; act0[4 * q + 2] = f0.z; act0[4 * q + 3] = f0.w;
            act1[4 * q + 0] = f1.x; act1[4 * q + 1] = f1.y; act1[4 * q + 2] = f1.z; act1[4 * q + 3] = f1.w;
        }
    }

    // ---- bank apply: out[o] = sum_w cf[w] * sum_k feat[k]*bank[w, k*32+o] ----
#pragma unroll
    for (int j = 0; j < 16; j++) { acc0[j] = 0ull; acc1[j] = 0ull; }

    for (int w = 0; w < 8; w++) {
        float c0 = act0[32 + w];
        float c1 = act1[32 + w];
        const float* bw = &sm[OFF_BANK + w * 1024];
#pragma unroll 4
        for (int k = 0; k < 32; k++) {
            fma_row(acc0, acc1, dup2(c0 * act0[k]), dup2(c1 * act1[k]), &bw[k * 32]);
        }
    }

    // ---- store [32] fp32 per point ----
    float4* op0 = reinterpret_cast<float4*>(out + (size_t)i0 * 32);
    float4* op1 = reinterpret_cast<float4*>(out + (size_t)i1 * 32);
#pragma unroll
    for (int q = 0; q < 8; q++) {
        float2 a = unpk(acc0[2 * q]), b = unpk(acc0[2 * q + 1]);
        op0[q] = make_float4(a.x, a.y, b.x, b.y);
    }
#pragma unroll
    for (int q = 0; q < 8; q++) {
        float2 a = unpk(acc1[2 * q]), b = unpk(acc1[2 * q + 1]);
        op1[q] = make_float4(a.x, a.y, b.x, b.y);
    }
}

extern "C" void kernel_launch(void* const* d_in, const int* in_sizes, int n_in,
                              void* d_out, int out_size) {
    const float* rel  = (const float*)d_in[0];
    const float* feat = (const float*)d_in[1];
    const float* w0 = (const float*)d_in[2];  const float* b0 = (const float*)d_in[3];
    const float* w1 = (const float*)d_in[4];  const float* b1 = (const float*)d_in[5];
    const float* w2 = (const float*)d_in[6];  const float* b2 = (const float*)d_in[7];
    const float* w3 = (const float*)d_in[8];  const float* b3 = (const float*)d_in[9];
    const float* w4 = (const float*)d_in[10]; const float* b4 = (const float*)d_in[11];
    const float* w5 = (const float*)d_in[12]; const float* b5 = (const float*)d_in[13];
    const float* bank = (const float*)d_in[14];

    int n = in_sizes[0] / 60;
    size_t smem = (size_t)SMEM_FLOATS * sizeof(float);  // (14632 + 128*2*41)*4 = 100,512 B

    cudaFuncSetAttribute(pointconv_fused_kernel,
                         cudaFuncAttributeMaxDynamicSharedMemorySize, (int)smem);

    int pts_per_blk = TPB * PPT;
    dim3 grid((n + pts_per_blk - 1) / pts_per_blk);
    pointconv_fused_kernel<<<grid, TPB, smem>>>(
        rel, feat, w0, b0, w1, b1, w2, b2, w3, b3, w4, b4, w5, b5, bank,
        (float*)d_out, n);
}

// round 3
// speedup vs baseline: 1.4293x; 1.0049x over previous
#include <cuda_runtime.h>

#define TPB 128
#define PPT 2            // points per thread
#define NEG_SLOPE 0.01f

// ---- shared-memory layout (float offsets) ----
#define OFF_W0   0        // 60*32 = 1920
#define OFF_B0   1920     // 32
#define OFF_W1   1952     // 4 hidden layers: (1024 w + 32 b) each
#define HID_STRIDE 1056
#define OFF_W5   6176     // 32*8 = 256
#define OFF_B5   6432     // 8
#define OFF_BANK 6440     // 8*1024 = 8192
#define PARAM_FLOATS 14632
#define OFF_ACT  PARAM_FLOATS
#define ACT_STRIDE 41     // 32 acts/feat + 8 coeffs + 1 pad; gcd(41,32)=1 -> conflict-free
#define SMEM_FLOATS (PARAM_FLOATS + TPB * PPT * ACT_STRIDE)

typedef unsigned long long u64;

__device__ __forceinline__ u64 ffma2(u64 a, u64 b, u64 c) {
    u64 d;
    asm("fma.rn.f32x2 %0, %1, %2, %3;" : "=l"(d) : "l"(a), "l"(b), "l"(c));
    return d;
}
__device__ __forceinline__ u64 dup2(float x) {
    u64 d;
    asm("mov.b64 %0, {%1, %2};" : "=l"(d) : "f"(x), "f"(x));
    return d;
}
__device__ __forceinline__ float2 unpk(u64 d) {
    float2 r;
    asm("mov.b64 {%0, %1}, %2;" : "=f"(r.x), "=f"(r.y) : "l"(d));
    return r;
}
__device__ __forceinline__ float lrelu(float v) { return fmaxf(v, NEG_SLOPE * v); }

// acc{0,1}[16 pairs] += dup(x{0,1}) * wrow[32 floats]; weight pairs come free from LDS.128
__device__ __forceinline__ void fma_row(u64 acc0[16], u64 acc1[16],
                                        u64 x0, u64 x1, const float* wrow) {
    const ulonglong2* wr = reinterpret_cast<const ulonglong2*>(wrow);
#pragma unroll
    for (int j = 0; j < 8; j++) {
        ulonglong2 w = wr[j];
        acc0[2 * j]     = ffma2(x0, w.x, acc0[2 * j]);
        acc0[2 * j + 1] = ffma2(x0, w.y, acc0[2 * j + 1]);
        acc1[2 * j]     = ffma2(x1, w.x, acc1[2 * j]);
        acc1[2 * j + 1] = ffma2(x1, w.y, acc1[2 * j + 1]);
    }
}

__global__ __launch_bounds__(TPB, 2)
void pointconv_fused_kernel(
    const float* __restrict__ rel,   // [n,60]
    const float* __restrict__ feat,  // [n,32]
    const float* __restrict__ w0, const float* __restrict__ b0,
    const float* __restrict__ w1, const float* __restrict__ b1,
    const float* __restrict__ w2, const float* __restrict__ b2,
    const float* __restrict__ w3, const float* __restrict__ b3,
    const float* __restrict__ w4, const float* __restrict__ b4,
    const float* __restrict__ w5, const float* __restrict__ b5,
    const float* __restrict__ bank,  // [8,1024]
    float* __restrict__ out,         // [n,32]
    int n)
{
    extern __shared__ float sm[];
    const int tid = threadIdx.x;

    // ---- cooperative param staging ----
#define CP(off, src, cnt) for (int t = tid; t < (cnt); t += TPB) sm[(off) + t] = (src)[t];
    CP(OFF_W0, w0, 1920)
    CP(OFF_B0, b0, 32)
    CP(OFF_W1 + 0 * HID_STRIDE, w1, 1024) CP(OFF_W1 + 0 * HID_STRIDE + 1024, b1, 32)
    CP(OFF_W1 + 1 * HID_STRIDE, w2, 1024) CP(OFF_W1 + 1 * HID_STRIDE + 1024, b2, 32)
    CP(OFF_W1 + 2 * HID_STRIDE, w3, 1024) CP(OFF_W1 + 2 * HID_STRIDE + 1024, b3, 32)
    CP(OFF_W1 + 3 * HID_STRIDE, w4, 1024) CP(OFF_W1 + 3 * HID_STRIDE + 1024, b4, 32)
    CP(OFF_W5, w5, 256)
    CP(OFF_B5, b5, 8)
    CP(OFF_BANK, bank, 8192)
#undef CP
    __syncthreads();

    const int i0 = blockIdx.x * (TPB * PPT) + tid;   // first point
    const int i1 = i0 + TPB;                          // second point (coalesced)
    if (i1 >= n && i0 >= n) return;

    float* act0 = &sm[OFF_ACT + (0 * TPB + tid) * ACT_STRIDE];
    float* act1 = &sm[OFF_ACT + (1 * TPB + tid) * ACT_STRIDE];

    u64 acc0[16], acc1[16];

    // ---- layer 0: 60 -> 32 ----
    {
        const float4* rp0 = reinterpret_cast<const float4*>(rel + (size_t)i0 * 60);
        const float4* rp1 = reinterpret_cast<const float4*>(rel + (size_t)i1 * 60);
        const ulonglong2* bp = reinterpret_cast<const ulonglong2*>(&sm[OFF_B0]);
#pragma unroll
        for (int j = 0; j < 8; j++) {
            ulonglong2 b = bp[j];
            acc0[2 * j] = b.x; acc0[2 * j + 1] = b.y;
            acc1[2 * j] = b.x; acc1[2 * j + 1] = b.y;
        }
        for (int k4 = 0; k4 < 15; k4++) {
            float4 a0 = rp0[k4];
            float4 a1 = rp1[k4];
            const float* wrow = &sm[OFF_W0 + (k4 * 4) * 32];
            fma_row(acc0, acc1, dup2(a0.x), dup2(a1.x), wrow + 0 * 32);
            fma_row(acc0, acc1, dup2(a0.y), dup2(a1.y), wrow + 1 * 32);
            fma_row(acc0, acc1, dup2(a0.z), dup2(a1.z), wrow + 2 * 32);
            fma_row(acc0, acc1, dup2(a0.w), dup2(a1.w), wrow + 3 * 32);
        }
#pragma unroll
        for (int j = 0; j < 16; j++) {
            float2 v0 = unpk(acc0[j]), v1 = unpk(acc1[j]);
            act0[2 * j] = lrelu(v0.x); act0[2 * j + 1] = lrelu(v0.y);
            act1[2 * j] = lrelu(v1.x); act1[2 * j + 1] = lrelu(v1.y);
        }
    }

    // ---- hidden layers 1..4: 32 -> 32 ----
    for (int L = 0; L < 4; L++) {
        const float* wb = &sm[OFF_W1 + L * HID_STRIDE];
        const ulonglong2* bp = reinterpret_cast<const ulonglong2*>(&wb[1024]);
#pragma unroll
        for (int j = 0; j < 8; j++) {
            ulonglong2 b = bp[j];
            acc0[2 * j] = b.x; acc0[2 * j + 1] = b.y;
            acc1[2 * j] = b.x; acc1[2 * j + 1] = b.y;
        }
#pragma unroll 4
        for (int k = 0; k < 32; k++) {
            fma_row(acc0, acc1, dup2(act0[k]), dup2(act1[k]), &wb[k * 32]);
        }
#pragma unroll
        for (int j = 0; j < 16; j++) {
            float2 v0 = unpk(acc0[j]), v1 = unpk(acc1[j]);
            act0[2 * j] = lrelu(v0.x); act0[2 * j + 1] = lrelu(v0.y);
            act1[2 * j] = lrelu(v1.x); act1[2 * j + 1] = lrelu(v1.y);
        }
    }

    // ---- layer 5: 32 -> 8 logits (pairs over the 8 outputs) ----
    u64 lg0[4], lg1[4];
    {
        const ulonglong2* bp = reinterpret_cast<const ulonglong2*>(&sm[OFF_B5]);
        ulonglong2 b0p = bp[0], b1p = bp[1];
        lg0[0] = b0p.x; lg0[1] = b0p.y; lg0[2] = b1p.x; lg0[3] = b1p.y;
        lg1[0] = b0p.x; lg1[1] = b0p.y; lg1[2] = b1p.x; lg1[3] = b1p.y;
#pragma unroll 4
        for (int k = 0; k < 32; k++) {
            u64 x0 = dup2(act0[k]), x1 = dup2(act1[k]);
            const ulonglong2* wr = reinterpret_cast<const ulonglong2*>(&sm[OFF_W5 + k * 8]);
            ulonglong2 wa = wr[0], wb2 = wr[1];
            lg0[0] = ffma2(x0, wa.x, lg0[0]); lg0[1] = ffma2(x0, wa.y, lg0[1]);
            lg0[2] = ffma2(x0, wb2.x, lg0[2]); lg0[3] = ffma2(x0, wb2.y, lg0[3]);
            lg1[0] = ffma2(x1, wa.x, lg1[0]); lg1[1] = ffma2(x1, wa.y, lg1[1]);
            lg1[2] = ffma2(x1, wb2.x, lg1[2]); lg1[3] = ffma2(x1, wb2.y, lg1[3]);
        }
    }

    // ---- softmax over 8 (scalar fp32); coeffs parked at act[32..39] ----
    {
        float l0[8], l1[8];
#pragma unroll
        for (int j = 0; j < 4; j++) {
            float2 v0 = unpk(lg0[j]), v1 = unpk(lg1[j]);
            l0[2 * j] = v0.x; l0[2 * j + 1] = v0.y;
            l1[2 * j] = v1.x; l1[2 * j + 1] = v1.y;
        }
        float m0 = l0[0], m1 = l1[0];
#pragma unroll
        for (int w = 1; w < 8; w++) { m0 = fmaxf(m0, l0[w]); m1 = fmaxf(m1, l1[w]); }
        float s0 = 0.f, s1 = 0.f;
#pragma unroll
        for (int w = 0; w < 8; w++) {
            l0[w] = __expf(l0[w] - m0); s0 += l0[w];
            l1[w] = __expf(l1[w] - m1); s1 += l1[w];
        }
        float r0 = 1.0f / s0, r1 = 1.0f / s1;
#pragma unroll
        for (int w = 0; w < 8; w++) { act0[32 + w] = l0[w] * r0; act1[32 + w] = l1[w] * r1; }
    }

    // ---- copy feat into act[0..31] (acts dead now) ----
    {
        const float4* fp0 = reinterpret_cast<const float4*>(feat + (size_t)i0 * 32);
        const float4* fp1 = reinterpret_cast<const float4*>(feat + (size_t)i1 * 32);
#pragma unroll
        for (int q = 0; q < 8; q++) {
            float4 f0 = fp0[q], f1 = fp1[q];
            act0[4 * q + 0] = f0.x; act0[4 * q + 1] = f0.y; act0[4 * q + 2] = f0.z; act0[4 * q + 3] = f0.w;
            act1[4 * q + 0] = f1.x; act1[4 * q + 1] = f1.y; act1[4 * q + 2] = f1.z; act1[4 * q + 3] = f1.w;
        }
    }

    // ---- bank apply: out[o] = sum_w cf[w] * sum_k feat[k]*bank[w, k*32+o] ----
#pragma unroll
    for (int j = 0; j < 16; j++) { acc0[j] = 0ull; acc1[j] = 0ull; }

    for (int w = 0; w < 8; w++) {
        float c0 = act0[32 + w];
        float c1 = act1[32 + w];
        const float* bw = &sm[OFF_BANK + w * 1024];
#pragma unroll 4
        for (int k = 0; k < 32; k++) {
            fma_row(acc0, acc1, dup2(c0 * act0[k]), dup2(c1 * act1[k]), &bw[k * 32]);
        }
    }

    // ---- store [32] fp32 per point ----
    float4* op0 = reinterpret_cast<float4*>(out + (size_t)i0 * 32);
    float4* op1 = reinterpret_cast<float4*>(out + (size_t)i1 * 32);
#pragma unroll
    for (int q = 0; q < 8; q++) {
        float2 a = unpk(acc0[2 * q]), b = unpk(acc0[2 * q + 1]);
        op0[q] = make_float4(a.x, a.y, b.x, b.y);
    }
#pragma unroll
    for (int q = 0; q < 8; q++) {
        float2 a = unpk(acc1[2 * q]), b = unpk(acc1[2 * q + 1]);
        op1[q] = make_float4(a.x, a.y, b.x, b.y);
    }
}

extern "C" void kernel_launch(void* const* d_in, const int* in_sizes, int n_in,
                              void* d_out, int out_size) {
    const float* rel  = (const float*)d_in[0];
    const float* feat = (const float*)d_in[1];
    const float* w0 = (const float*)d_in[2];  const float* b0 = (const float*)d_in[3];
    const float* w1 = (const float*)d_in[4];  const float* b1 = (const float*)d_in[5];
    const float* w2 = (const float*)d_in[6];  const float* b2 = (const float*)d_in[7];
    const float* w3 = (const float*)d_in[8];  const float* b3 = (const float*)d_in[9];
    const float* w4 = (const float*)d_in[10]; const float* b4 = (const float*)d_in[11];
    const float* w5 = (const float*)d_in[12]; const float* b5 = (const float*)d_in[13];
    const float* bank = (const float*)d_in[14];

    int n = in_sizes[0] / 60;
    size_t smem = (size_t)SMEM_FLOATS * sizeof(float);  // (14632 + 128*2*41)*4 = 100,512 B

    cudaFuncSetAttribute(pointconv_fused_kernel,
                         cudaFuncAttributeMaxDynamicSharedMemorySize, (int)smem);

    int pts_per_blk = TPB * PPT;
    dim3 grid((n + pts_per_blk - 1) / pts_per_blk);
    pointconv_fused_kernel<<<grid, TPB, smem>>>(
        rel, feat, w0, b0, w1, b1, w2, b2, w3, b3, w4, b4, w5, b5, bank,
        (float*)d_out, n);
}